// round 5
// baseline (speedup 1.0000x reference)
#include <cuda_runtime.h>
#include <math.h>

#define TLEN    2048
#define HEADS_N 8
#define BATCH   2
#define SDIM    64
#define EDIM    512

// ---------------- scratch + resolved input pointers (device-resident) ----------
__device__ float g_q[BATCH*HEADS_N*TLEN*SDIM];
__device__ float g_k[BATCH*HEADS_N*TLEN*SDIM];
__device__ float g_v[BATCH*HEADS_N*TLEN*SDIM];
__device__ float g_vmean[BATCH*HEADS_N*SDIM];
__device__ float g_attn[BATCH*TLEN*EDIM];

__device__ const float*        g_pWq;
__device__ const float*        g_pWk;
__device__ const float*        g_pWv;
__device__ const unsigned int* g_pmask;

// ---------------- prologue: content-based identification of mask ---------------
__global__ void select_inputs(const float* c0, const float* c1,
                              const float* c2, const float* c3, int x_first) {
    __shared__ int bad[4];
    const float* cand[4] = {c0, c1, c2, c3};
    if (threadIdx.x < 4) bad[threadIdx.x] = 0;
    __syncthreads();
    for (int j = 0; j < 4; j++) {
        const unsigned int* p = (const unsigned int*)cand[j];
        int b = 0;
        for (int i = threadIdx.x; i < SDIM*SDIM; i += blockDim.x) {
            unsigned int v = p[i];
            if (v != 0u && v != 1u && v != 0x3F800000u) { b = 1; break; }
        }
        if (b) atomicOr(&bad[j], 1);
    }
    __syncthreads();
    if (threadIdx.x == 0) {
        int mi = -1;
        for (int j = 0; j < 4; j++) if (!bad[j]) { mi = j; break; }
        if (mi < 0) mi = x_first ? 0 : 3;
        const float* rest[3]; int n = 0;
        for (int j = 0; j < 4; j++) if (j != mi) rest[n++] = cand[j];
        g_pmask = (const unsigned int*)cand[mi];
        if (x_first) { g_pWq = rest[0]; g_pWk = rest[1]; g_pWv = rest[2]; }
        else         { g_pWk = rest[0]; g_pWq = rest[1]; g_pWv = rest[2]; }
    }
}

// ---------------- QKV projection ----------------
// grid: (TLEN/128, H, B), 256 threads
__global__ void proj_kernel(const float* __restrict__ x) {
    extern __shared__ float sm[];
    float* sW = sm;              // 3*64 rows, stride 65
    float* sX = sm + 3*64*65;    // 128 rows, stride 65
    const int t0 = blockIdx.x * 128;
    const int h  = blockIdx.y;
    const int b  = blockIdx.z;
    const int tid = threadIdx.x;
    const float* Wq = g_pWq;
    const float* Wk = g_pWk;
    const float* Wv = g_pWv;

    for (int k = tid; k < 64*64; k += 256) {
        int o = k >> 6, i = k & 63;
        sW[o*65 + i]         = Wq[k];
        sW[(64 + o)*65 + i]  = Wk[k];
        sW[(128 + o)*65 + i] = Wv[k];
    }
    for (int k = tid; k < 128*64; k += 256) {
        int row = k >> 6, i = k & 63;
        sX[row*65 + i] = x[(size_t)(b*TLEN + t0 + row)*EDIM + h*SDIM + i];
    }
    __syncthreads();

    for (int idx = tid; idx < 128*192; idx += 256) {
        int row = idx / 192;
        int rem = idx - row*192;
        int mm  = rem >> 6;
        int o   = rem & 63;
        const float* w  = &sW[(mm*64 + o)*65];
        const float* xr = &sX[row*65];
        float a = 0.f;
        #pragma unroll
        for (int i = 0; i < 64; i++) a = fmaf(xr[i], w[i], a);
        float* dst = (mm == 0) ? g_q : (mm == 1) ? g_k : g_v;
        dst[((size_t)(b*HEADS_N + h)*TLEN + t0 + row)*SDIM + o] = a;
    }
}

// ---------------- V mean (for masked query rows) ----------------
__global__ void vmean_kernel() {
    const int bh  = blockIdx.x;
    const int tid = threadIdx.x;
    const int d   = tid & 63;
    const int ch  = tid >> 6;
    __shared__ float red[4][64];
    float a = 0.f;
    for (int l = ch; l < TLEN; l += 4)
        a += g_v[((size_t)bh*TLEN + l)*SDIM + d];
    red[ch][d] = a;
    __syncthreads();
    if (ch == 0)
        g_vmean[bh*SDIM + d] =
            (red[0][d] + red[1][d] + red[2][d] + red[3][d]) * (1.f/(float)TLEN);
}

// ---------------- fused flash attention with relative position ----------------
// grid: (TLEN/64, H, B), 256 threads (16x16, 4x4 micro-tile)
// scores[i,c] = 512^-0.5 * q_i.k_c + q_i . Er[h, t-1-(i-c)]  for c <= i
//
// IMPORTANT: the reference's einsum('...->bths') + transpose(0,2,1,3) +
// reshape(b,t,e) scrambles the head-concat. Per batch, attention output
// O[b,t,h,s] lands in the pre-Wo matrix at row R = h*256 + (t>>3),
// col C = (t&7)*64 + s. We replicate that layout when writing g_attn.
__global__ void attn_kernel(const float* __restrict__ Er) {
    extern __shared__ float sm[];
    float* sQ  = sm;                 // 64 x 65
    float* sK  = sQ  + 64*65;        // 64 x 65 (pre-scaled)
    float* sV  = sK  + 64*65;        // 64 x 65
    float* sEr = sV  + 64*65;        // 127 x 65
    float* sP  = sEr + 127*65;       // 64 x 65

    const int i0 = blockIdx.x * 64;
    const int h  = blockIdx.y;
    const int b  = blockIdx.z;
    const int tid = threadIdx.x;
    const int tx = tid & 15;
    const int ty = tid >> 4;
    const float scale2 = 0.04419417382415922f;   // 512^-0.5

    const float* gq = g_q + (size_t)(b*HEADS_N + h)*TLEN*SDIM;
    const float* gk = g_k + (size_t)(b*HEADS_N + h)*TLEN*SDIM;
    const float* gv = g_v + (size_t)(b*HEADS_N + h)*TLEN*SDIM;

    for (int k = tid; k < 64*64; k += 256) {
        int li = k >> 6, s = k & 63;
        sQ[li*65 + s] = gq[(i0 + li)*SDIM + s];
    }

    float m[4], l[4], O[4][4];
    #pragma unroll
    for (int r = 0; r < 4; r++) {
        m[r] = -1e30f; l[r] = 0.f;
        #pragma unroll
        for (int c = 0; c < 4; c++) O[r][c] = 0.f;
    }

    const int nt = (i0 >> 6) + 1;
    const int obase = 63 + 4*(tx - ty);    // in [3, 123]

    for (int ct = 0; ct < nt; ct++) {
        const int c0 = ct * 64;
        __syncthreads();

        for (int k = tid; k < 64*64; k += 256) {
            int lc = k >> 6, s = k & 63;
            sK[lc*65 + s] = gk[(c0 + lc)*SDIM + s] * scale2;
            sV[lc*65 + s] = gv[(c0 + lc)*SDIM + s];
        }
        const int jbase = TLEN - 64 - i0 + c0;     // >= 0
        for (int k = tid; k < 127*64; k += 256) {
            int off = k >> 6, s = k & 63;
            int j = jbase + off;
            sEr[off*65 + s] = (j < TLEN) ? Er[((size_t)h*TLEN + j)*SDIM + s] : 0.f;
        }
        __syncthreads();

        float acc[4][4];
        #pragma unroll
        for (int r = 0; r < 4; r++)
            #pragma unroll
            for (int c = 0; c < 4; c++) acc[r][c] = 0.f;

        #pragma unroll 8
        for (int s = 0; s < 64; s++) {
            float rq[4], rk[4], re[7];
            #pragma unroll
            for (int r = 0; r < 4; r++) rq[r] = sQ[(ty*4 + r)*65 + s];
            #pragma unroll
            for (int c = 0; c < 4; c++) rk[c] = sK[(tx*4 + c)*65 + s];
            #pragma unroll
            for (int k = 0; k < 7; k++) re[k] = sEr[(obase - 3 + k)*65 + s];
            #pragma unroll
            for (int r = 0; r < 4; r++)
                #pragma unroll
                for (int c = 0; c < 4; c++)
                    acc[r][c] = fmaf(rq[r], rk[c] + re[3 + c - r], acc[r][c]);
        }

        if (c0 == i0) {   // diagonal tile: causal mask
            #pragma unroll
            for (int r = 0; r < 4; r++)
                #pragma unroll
                for (int c = 0; c < 4; c++)
                    if (c0 + tx*4 + c > i0 + ty*4 + r) acc[r][c] = -1e30f;
        }

        #pragma unroll
        for (int r = 0; r < 4; r++) {
            float rowmax = fmaxf(fmaxf(acc[r][0], acc[r][1]),
                                 fmaxf(acc[r][2], acc[r][3]));
            #pragma unroll
            for (int off = 8; off > 0; off >>= 1)
                rowmax = fmaxf(rowmax, __shfl_xor_sync(0xffffffffu, rowmax, off));
            float mnew = fmaxf(m[r], rowmax);
            float corr = expf(m[r] - mnew);
            float ps = 0.f;
            #pragma unroll
            for (int c = 0; c < 4; c++) {
                float p = expf(acc[r][c] - mnew);
                acc[r][c] = p;
                ps += p;
            }
            #pragma unroll
            for (int off = 8; off > 0; off >>= 1)
                ps += __shfl_xor_sync(0xffffffffu, ps, off);
            l[r] = l[r]*corr + ps;
            m[r] = mnew;
            #pragma unroll
            for (int c = 0; c < 4; c++) O[r][c] *= corr;
        }

        #pragma unroll
        for (int r = 0; r < 4; r++)
            #pragma unroll
            for (int c = 0; c < 4; c++)
                sP[(ty*4 + r)*65 + tx*4 + c] = acc[r][c];
        __syncthreads();

        #pragma unroll 8
        for (int lc = 0; lc < 64; lc++) {
            float rp[4], rv[4];
            #pragma unroll
            for (int r = 0; r < 4; r++) rp[r] = sP[(ty*4 + r)*65 + lc];
            #pragma unroll
            for (int c = 0; c < 4; c++) rv[c] = sV[lc*65 + tx*4 + c];
            #pragma unroll
            for (int r = 0; r < 4; r++)
                #pragma unroll
                for (int c = 0; c < 4; c++)
                    O[r][c] = fmaf(rp[r], rv[c], O[r][c]);
        }
    }

    // epilogue: scrambled layout R = h*256 + (i>>3), C = (i&7)*64 + d
    #pragma unroll
    for (int r = 0; r < 4; r++) {
        const int i  = i0 + ty*4 + r;
        const unsigned int mk = g_pmask[b*TLEN + i];   // bits!=0 covers int/float 0/1
        const float inv = 1.f / l[r];
        const int R = h*256 + (i >> 3);
        const int Cbase = (i & 7) << 6;
        #pragma unroll
        for (int c = 0; c < 4; c++) {
            const int d = tx*4 + c;
            float val = (mk != 0u) ? O[r][c] * inv
                                   : g_vmean[(b*HEADS_N + h)*SDIM + d];
            g_attn[((size_t)(b*TLEN) + R)*EDIM + Cbase + d] = val;
        }
    }
}

// ---------------- output projection: out = attnS @ Wo^T + bo -------------------
__global__ void outproj_kernel(const float* __restrict__ Wo,
                               const float* __restrict__ bo,
                               float* __restrict__ out) {
    __shared__ float sA[64*65];
    __shared__ float sB[64*65];
    const int m0 = blockIdx.x * 64;
    const int n0 = blockIdx.y * 64;
    const int tid = threadIdx.x;
    const int tx = tid & 15;
    const int ty = tid >> 4;

    float acc[4][4];
    #pragma unroll
    for (int r = 0; r < 4; r++)
        #pragma unroll
        for (int c = 0; c < 4; c++) acc[r][c] = 0.f;

    for (int kc = 0; kc < EDIM; kc += 64) {
        __syncthreads();
        for (int k = tid; k < 64*64; k += 256) {
            int rr = k >> 6, cc = k & 63;
            sA[rr*65 + cc] = g_attn[(size_t)(m0 + rr)*EDIM + kc + cc];
            sB[rr*65 + cc] = Wo[(size_t)(n0 + rr)*EDIM + kc + cc];
        }
        __syncthreads();
        #pragma unroll 8
        for (int s = 0; s < 64; s++) {
            float ra[4], rb[4];
            #pragma unroll
            for (int r = 0; r < 4; r++) ra[r] = sA[(ty*4 + r)*65 + s];
            #pragma unroll
            for (int c = 0; c < 4; c++) rb[c] = sB[(tx*4 + c)*65 + s];
            #pragma unroll
            for (int r = 0; r < 4; r++)
                #pragma unroll
                for (int c = 0; c < 4; c++)
                    acc[r][c] = fmaf(ra[r], rb[c], acc[r][c]);
        }
    }

    #pragma unroll
    for (int r = 0; r < 4; r++)
        #pragma unroll
        for (int c = 0; c < 4; c++)
            out[(size_t)(m0 + ty*4 + r)*EDIM + n0 + tx*4 + c] =
                acc[r][c] + bo[n0 + tx*4 + c];
}

// ---------------- launch ----------------
extern "C" void kernel_launch(void* const* d_in, const int* in_sizes, int n_in,
                              void* d_out, int out_size) {
    int idx_x = -1, idx_Er = -1, idx_Wo = -1, idx_bo = -1;
    int cand[8]; int ncand = 0;
    for (int scale = 1; scale <= 4; scale *= 4) {
        idx_x = idx_Er = idx_Wo = idx_bo = -1; ncand = 0;
        for (int i = 0; i < n_in; i++) {
            long long s = in_sizes[i];
            if      (s == (long long)BATCH*TLEN*EDIM*scale)   idx_x  = i;
            else if (s == (long long)HEADS_N*TLEN*SDIM*scale) idx_Er = i;
            else if (s == (long long)EDIM*EDIM*scale)         idx_Wo = i;
            else if (s == (long long)EDIM*scale)              idx_bo = i;
            else if (s == (long long)SDIM*SDIM*scale && ncand < 8) cand[ncand++] = i;
        }
        if (idx_x >= 0 && idx_Er >= 0 && idx_Wo >= 0 && idx_bo >= 0 && ncand == 4)
            break;
    }
    if (!(idx_x >= 0 && idx_Er >= 0 && idx_Wo >= 0 && idx_bo >= 0 && ncand == 4)) {
        int wi = (n_in >= 9) ? 3 : 2;
        idx_x = 0; cand[0] = 1; cand[1] = wi; cand[2] = wi + 1; cand[3] = wi + 2;
        idx_Er = wi + 3; idx_Wo = wi + 4; idx_bo = wi + 5; ncand = 4;
    }

    const float* x  = (const float*)d_in[idx_x];
    const float* Er = (const float*)d_in[idx_Er];
    const float* Wo = (const float*)d_in[idx_Wo];
    const float* bo = (const float*)d_in[idx_bo];
    float* out = (float*)d_out;

    const int PROJ_SMEM = (3*64*65 + 128*65) * (int)sizeof(float);   // 83200 B
    const int ATTN_SMEM = (4*64*65 + 127*65) * (int)sizeof(float);   // 99580 B
    cudaFuncSetAttribute(proj_kernel, cudaFuncAttributeMaxDynamicSharedMemorySize, PROJ_SMEM);
    cudaFuncSetAttribute(attn_kernel, cudaFuncAttributeMaxDynamicSharedMemorySize, ATTN_SMEM);

    select_inputs<<<1, 256>>>((const float*)d_in[cand[0]], (const float*)d_in[cand[1]],
                              (const float*)d_in[cand[2]], (const float*)d_in[cand[3]],
                              (idx_x == 0) ? 1 : 0);
    proj_kernel<<<dim3(TLEN/128, HEADS_N, BATCH), 256, PROJ_SMEM>>>(x);
    vmean_kernel<<<BATCH*HEADS_N, 256>>>();
    attn_kernel<<<dim3(TLEN/64, HEADS_N, BATCH), 256, ATTN_SMEM>>>(Er);
    outproj_kernel<<<dim3((BATCH*TLEN)/64, EDIM/64), 256>>>(Wo, bo, out);
}

// round 6
// speedup vs baseline: 1.2416x; 1.2416x over previous
#include <cuda_runtime.h>
#include <math.h>

#define TLEN    2048
#define HEADS_N 8
#define BATCH   2
#define SDIM    64
#define EDIM    512

// ---------------- scratch + resolved input pointers (device-resident) ----------
__device__ float g_q[BATCH*HEADS_N*TLEN*SDIM];
__device__ float g_k[BATCH*HEADS_N*TLEN*SDIM];
__device__ float g_v[BATCH*HEADS_N*TLEN*SDIM];
__device__ float g_vmean[BATCH*HEADS_N*SDIM];
__device__ float g_attn[BATCH*TLEN*EDIM];

__device__ const float*        g_pWq;
__device__ const float*        g_pWk;
__device__ const float*        g_pWv;
__device__ const unsigned int* g_pmask;

// ---------------- prologue: content-based identification of mask ---------------
__global__ void select_inputs(const float* c0, const float* c1,
                              const float* c2, const float* c3, int x_first) {
    __shared__ int bad[4];
    const float* cand[4] = {c0, c1, c2, c3};
    if (threadIdx.x < 4) bad[threadIdx.x] = 0;
    __syncthreads();
    for (int j = 0; j < 4; j++) {
        const unsigned int* p = (const unsigned int*)cand[j];
        int b = 0;
        for (int i = threadIdx.x; i < SDIM*SDIM; i += blockDim.x) {
            unsigned int v = p[i];
            if (v != 0u && v != 1u && v != 0x3F800000u) { b = 1; break; }
        }
        if (b) atomicOr(&bad[j], 1);
    }
    __syncthreads();
    if (threadIdx.x == 0) {
        int mi = -1;
        for (int j = 0; j < 4; j++) if (!bad[j]) { mi = j; break; }
        if (mi < 0) mi = x_first ? 0 : 3;
        const float* rest[3]; int n = 0;
        for (int j = 0; j < 4; j++) if (j != mi) rest[n++] = cand[j];
        g_pmask = (const unsigned int*)cand[mi];
        if (x_first) { g_pWq = rest[0]; g_pWk = rest[1]; g_pWv = rest[2]; }
        else         { g_pWk = rest[0]; g_pWq = rest[1]; g_pWv = rest[2]; }
    }
}

// ---------------- QKV projection (swizzled float4 smem) ----------------
// grid: (TLEN/128, H, B), 256 threads
__global__ void proj_kernel(const float* __restrict__ x) {
    extern __shared__ float sm[];
    float* sW = sm;              // 192 rows x 64, swizzled
    float* sX = sm + 192*64;     // 128 rows x 64, swizzled
    const int t0 = blockIdx.x * 128;
    const int h  = blockIdx.y;
    const int b  = blockIdx.z;
    const int tid = threadIdx.x;
    const float* W[3] = {g_pWq, g_pWk, g_pWv};

    // stage weights: row o (per matrix), swizzle mask = o&15
    for (int k = tid; k < 3*64*16; k += 256) {
        int row = k >> 4, i4 = k & 15;          // row in 0..191
        int mm = row >> 6, o = row & 63;
        float4 f = *(const float4*)&W[mm][o*SDIM + i4*4];
        *(float4*)&sW[row*64 + ((i4 ^ o) & 15)*4] = f;
    }
    for (int k = tid; k < 128*16; k += 256) {
        int row = k >> 4, i4 = k & 15;
        float4 f = *(const float4*)&x[(size_t)(b*TLEN + t0 + row)*EDIM + h*SDIM + i4*4];
        *(float4*)&sX[row*64 + ((i4 ^ (row & 15)) & 15)*4] = f;
    }
    __syncthreads();

    for (int idx = tid; idx < 128*192; idx += 256) {
        int row = idx / 192;                    // x row 0..127
        int rem = idx - row*192;                // 0..191 = weight row
        float a = 0.f;
        const int mw = rem & 15;                // weight swizzle mask (o&15)
        const int mx = row & 15;
        #pragma unroll
        for (int i4 = 0; i4 < 16; i4++) {
            float4 w4 = *(const float4*)&sW[rem*64 + ((i4 ^ mw) & 15)*4];
            float4 x4 = *(const float4*)&sX[row*64 + ((i4 ^ mx) & 15)*4];
            a = fmaf(w4.x, x4.x, a); a = fmaf(w4.y, x4.y, a);
            a = fmaf(w4.z, x4.z, a); a = fmaf(w4.w, x4.w, a);
        }
        int mm = rem >> 6, o = rem & 63;
        float* dst = (mm == 0) ? g_q : (mm == 1) ? g_k : g_v;
        dst[((size_t)(b*HEADS_N + h)*TLEN + t0 + row)*SDIM + o] = a;
    }
}

// ---------------- V mean (for masked query rows) ----------------
__global__ void vmean_kernel() {
    const int bh  = blockIdx.x;
    const int tid = threadIdx.x;
    const int d   = tid & 63;
    const int ch  = tid >> 6;
    __shared__ float red[4][64];
    float a = 0.f;
    for (int l = ch; l < TLEN; l += 4)
        a += g_v[((size_t)bh*TLEN + l)*SDIM + d];
    red[ch][d] = a;
    __syncthreads();
    if (ch == 0)
        g_vmean[bh*SDIM + d] =
            (red[0][d] + red[1][d] + red[2][d] + red[3][d]) * (1.f/(float)TLEN);
}

// ---------------- fused flash attention with relative position ----------------
// grid: (TLEN/64, H, B), 256 threads (16x16, 4x4 micro-tile)
// scores[i,c] = 512^-0.5 * q_i.k_c + q_i . Er[h, t-1-(i-c)]  for c <= i
// Output layout replicates reference transpose-reshape scramble:
//   O[b,t,h,s] -> pre-Wo row R = h*256 + (t>>3), col C = (t&7)*64 + s
__global__ void __launch_bounds__(256, 2) attn_kernel(const float* __restrict__ Er) {
    extern __shared__ float sm[];
    float* sQt = sm;               // [s][i]  64x64 swizzled
    float* sKt = sQt + 4096;       // [s][c]  64x64 swizzled (pre-scaled)
    float* sV  = sKt + 4096;       // [lc][d] 64x64 swizzled
    float* sPt = sV  + 4096;       // [lc][i] 64x64 swizzled
    float* sEr = sPt + 4096;       // [s][o]  64x128 swizzled (o: 0..126)

    const int i0 = blockIdx.x * 64;
    const int h  = blockIdx.y;
    const int b  = blockIdx.z;
    const int tid = threadIdx.x;
    const int tx = tid & 15;
    const int ty = tid >> 4;
    const float scale2 = 0.04419417382415922f;   // 512^-0.5

    const float* gq = g_q + (size_t)(b*HEADS_N + h)*TLEN*SDIM;
    const float* gk = g_k + (size_t)(b*HEADS_N + h)*TLEN*SDIM;
    const float* gv = g_v + (size_t)(b*HEADS_N + h)*TLEN*SDIM;

    // stage Q transposed+swizzled (once)
    for (int k = tid; k < 1024; k += 256) {
        int li = k >> 4, s4 = k & 15;
        float4 f = *(const float4*)&gq[(size_t)(i0 + li)*SDIM + s4*4];
        int base = s4*4*64 + (((li >> 2) ^ s4) & 15)*4 + (li & 3);
        sQt[base]       = f.x;
        sQt[base + 64]  = f.y;
        sQt[base + 128] = f.z;
        sQt[base + 192] = f.w;
    }

    float m[4], l[4], O[4][4];
    #pragma unroll
    for (int r = 0; r < 4; r++) {
        m[r] = -1e30f; l[r] = 0.f;
        #pragma unroll
        for (int c = 0; c < 4; c++) O[r][c] = 0.f;
    }

    const int nt = (i0 >> 6) + 1;
    const int e0l = 15 + tx - ty;      // logical col4 of re[0..3] (0..30)
    const int pc4 = ((ty ^ tx) & 15)*4;

    for (int ct = 0; ct < nt; ct++) {
        const int c0 = ct * 64;
        __syncthreads();   // prev iteration fully consumed (also covers Q staging)

        // stage K (transposed+swizzled, pre-scaled) and V (row-major swizzled)
        for (int k = tid; k < 1024; k += 256) {
            int li = k >> 4, s4 = k & 15;
            float4 f = *(const float4*)&gk[(size_t)(c0 + li)*SDIM + s4*4];
            int base = s4*4*64 + (((li >> 2) ^ s4) & 15)*4 + (li & 3);
            sKt[base]       = f.x * scale2;
            sKt[base + 64]  = f.y * scale2;
            sKt[base + 128] = f.z * scale2;
            sKt[base + 192] = f.w * scale2;
            float4 v = *(const float4*)&gv[(size_t)(c0 + li)*SDIM + s4*4];
            *(float4*)&sV[li*64 + ((s4 ^ (li >> 2)) & 15)*4] = v;
        }
        // stage Er rows jbase..jbase+126, transposed+swizzled
        const int jbase = TLEN - 64 - i0 + c0;     // >= 0
        for (int k = tid; k < 2032; k += 256) {
            int o = k >> 4, s4 = k & 15;
            int j = jbase + o;
            float4 f;
            if (j < TLEN) f = *(const float4*)&Er[((size_t)h*TLEN + j)*SDIM + s4*4];
            else          f = make_float4(0.f, 0.f, 0.f, 0.f);
            int c4s = ((o >> 2) & 16) | (((o >> 2) ^ s4) & 15);
            int base = s4*4*128 + c4s*4 + (o & 3);
            sEr[base]       = f.x;
            sEr[base + 128] = f.y;
            sEr[base + 256] = f.z;
            sEr[base + 384] = f.w;
        }
        __syncthreads();

        float acc[4][4];
        #pragma unroll
        for (int r = 0; r < 4; r++)
            #pragma unroll
            for (int c = 0; c < 4; c++) acc[r][c] = 0.f;

        #pragma unroll 4
        for (int s4 = 0; s4 < 16; s4++) {
            const int mq = ((ty ^ s4) & 15)*4;
            const int mk = ((tx ^ s4) & 15)*4;
            const int e0 = (((e0l & 16) | ((e0l ^ s4) & 15)))*4;
            const int e1l = e0l + 1;
            const int e1 = (((e1l & 16) | ((e1l ^ s4) & 15)))*4;
            #pragma unroll
            for (int j = 0; j < 4; j++) {
                const int s = s4*4 + j;
                float4 q4 = *(const float4*)&sQt[s*64 + mq];
                float4 k4 = *(const float4*)&sKt[s*64 + mk];
                float4 ea = *(const float4*)&sEr[s*128 + e0];
                float4 eb = *(const float4*)&sEr[s*128 + e1];
                float rq[4] = {q4.x, q4.y, q4.z, q4.w};
                float rk[4] = {k4.x, k4.y, k4.z, k4.w};
                float re[8] = {ea.x, ea.y, ea.z, ea.w, eb.x, eb.y, eb.z, eb.w};
                #pragma unroll
                for (int r = 0; r < 4; r++)
                    #pragma unroll
                    for (int c = 0; c < 4; c++)
                        acc[r][c] = fmaf(rq[r], rk[c] + re[3 + c - r], acc[r][c]);
            }
        }

        if (c0 == i0) {   // diagonal tile: causal mask
            #pragma unroll
            for (int r = 0; r < 4; r++)
                #pragma unroll
                for (int c = 0; c < 4; c++)
                    if (tx*4 + c > ty*4 + r) acc[r][c] = -1e30f;
        }

        // online softmax (rows owned by 16 lanes sharing ty)
        #pragma unroll
        for (int r = 0; r < 4; r++) {
            float rowmax = fmaxf(fmaxf(acc[r][0], acc[r][1]),
                                 fmaxf(acc[r][2], acc[r][3]));
            #pragma unroll
            for (int off = 8; off > 0; off >>= 1)
                rowmax = fmaxf(rowmax, __shfl_xor_sync(0xffffffffu, rowmax, off));
            float mnew = fmaxf(m[r], rowmax);
            float corr = __expf(m[r] - mnew);
            float ps = 0.f;
            #pragma unroll
            for (int c = 0; c < 4; c++) {
                float p = __expf(acc[r][c] - mnew);
                acc[r][c] = p;
                ps += p;
            }
            #pragma unroll
            for (int off = 8; off > 0; off >>= 1)
                ps += __shfl_xor_sync(0xffffffffu, ps, off);
            l[r] = l[r]*corr + ps;
            m[r] = mnew;
            #pragma unroll
            for (int c = 0; c < 4; c++) O[r][c] *= corr;
        }

        // stage P transposed+swizzled: row lc = tx*4+c, col i = ty*4+r
        #pragma unroll
        for (int c = 0; c < 4; c++)
            #pragma unroll
            for (int r = 0; r < 4; r++)
                sPt[(tx*4 + c)*64 + pc4 + r] = acc[r][c];
        __syncthreads();

        // O += P @ V
        #pragma unroll 4
        for (int l4 = 0; l4 < 16; l4++) {
            const int mp = ((ty ^ l4) & 15)*4;
            const int mv = ((tx ^ l4) & 15)*4;
            #pragma unroll
            for (int j = 0; j < 4; j++) {
                const int lc = l4*4 + j;
                float4 p4 = *(const float4*)&sPt[lc*64 + mp];
                float4 v4 = *(const float4*)&sV[lc*64 + mv];
                float rp[4] = {p4.x, p4.y, p4.z, p4.w};
                float rv[4] = {v4.x, v4.y, v4.z, v4.w};
                #pragma unroll
                for (int r = 0; r < 4; r++)
                    #pragma unroll
                    for (int c = 0; c < 4; c++)
                        O[r][c] = fmaf(rp[r], rv[c], O[r][c]);
            }
        }
    }

    // epilogue: scrambled layout R = h*256 + (i>>3), C = (i&7)*64 + d
    #pragma unroll
    for (int r = 0; r < 4; r++) {
        const int i  = i0 + ty*4 + r;
        const unsigned int mk = g_pmask[b*TLEN + i];
        const float inv = 1.f / l[r];
        const int R = h*256 + (i >> 3);
        const int Cbase = (i & 7) << 6;
        #pragma unroll
        for (int c = 0; c < 4; c++) {
            const int d = tx*4 + c;
            float val = (mk != 0u) ? O[r][c] * inv
                                   : g_vmean[(b*HEADS_N + h)*SDIM + d];
            g_attn[((size_t)(b*TLEN) + R)*EDIM + Cbase + d] = val;
        }
    }
}

// ---------------- output projection: out = attnS @ Wo^T + bo -------------------
__global__ void outproj_kernel(const float* __restrict__ Wo,
                               const float* __restrict__ bo,
                               float* __restrict__ out) {
    __shared__ float sAt[64*64];   // [s][m] swizzled
    __shared__ float sBt[64*64];   // [s][n] swizzled
    const int m0 = blockIdx.x * 64;
    const int n0 = blockIdx.y * 64;
    const int tid = threadIdx.x;
    const int tx = tid & 15;
    const int ty = tid >> 4;

    float acc[4][4];
    #pragma unroll
    for (int r = 0; r < 4; r++)
        #pragma unroll
        for (int c = 0; c < 4; c++) acc[r][c] = 0.f;

    for (int kc = 0; kc < EDIM; kc += 64) {
        __syncthreads();
        for (int k = tid; k < 1024; k += 256) {
            int rr = k >> 4, c4 = k & 15;
            float4 a = *(const float4*)&g_attn[(size_t)(m0 + rr)*EDIM + kc + c4*4];
            int basea = c4*4*64 + (((rr >> 2) ^ c4) & 15)*4 + (rr & 3);
            sAt[basea]       = a.x;
            sAt[basea + 64]  = a.y;
            sAt[basea + 128] = a.z;
            sAt[basea + 192] = a.w;
            float4 bw = *(const float4*)&Wo[(size_t)(n0 + rr)*EDIM + kc + c4*4];
            sBt[basea]       = bw.x;
            sBt[basea + 64]  = bw.y;
            sBt[basea + 128] = bw.z;
            sBt[basea + 192] = bw.w;
        }
        __syncthreads();
        #pragma unroll 4
        for (int s4 = 0; s4 < 16; s4++) {
            const int ma = ((ty ^ s4) & 15)*4;
            const int mb = ((tx ^ s4) & 15)*4;
            #pragma unroll
            for (int j = 0; j < 4; j++) {
                const int s = s4*4 + j;
                float4 a4 = *(const float4*)&sAt[s*64 + ma];
                float4 b4 = *(const float4*)&sBt[s*64 + mb];
                float ra[4] = {a4.x, a4.y, a4.z, a4.w};
                float rb[4] = {b4.x, b4.y, b4.z, b4.w};
                #pragma unroll
                for (int r = 0; r < 4; r++)
                    #pragma unroll
                    for (int c = 0; c < 4; c++)
                        acc[r][c] = fmaf(ra[r], rb[c], acc[r][c]);
            }
        }
    }

    #pragma unroll
    for (int r = 0; r < 4; r++)
        #pragma unroll
        for (int c = 0; c < 4; c++)
            out[(size_t)(m0 + ty*4 + r)*EDIM + n0 + tx*4 + c] =
                acc[r][c] + bo[n0 + tx*4 + c];
}

// ---------------- launch ----------------
extern "C" void kernel_launch(void* const* d_in, const int* in_sizes, int n_in,
                              void* d_out, int out_size) {
    int idx_x = -1, idx_Er = -1, idx_Wo = -1, idx_bo = -1;
    int cand[8]; int ncand = 0;
    for (int scale = 1; scale <= 4; scale *= 4) {
        idx_x = idx_Er = idx_Wo = idx_bo = -1; ncand = 0;
        for (int i = 0; i < n_in; i++) {
            long long s = in_sizes[i];
            if      (s == (long long)BATCH*TLEN*EDIM*scale)   idx_x  = i;
            else if (s == (long long)HEADS_N*TLEN*SDIM*scale) idx_Er = i;
            else if (s == (long long)EDIM*EDIM*scale)         idx_Wo = i;
            else if (s == (long long)EDIM*scale)              idx_bo = i;
            else if (s == (long long)SDIM*SDIM*scale && ncand < 8) cand[ncand++] = i;
        }
        if (idx_x >= 0 && idx_Er >= 0 && idx_Wo >= 0 && idx_bo >= 0 && ncand == 4)
            break;
    }
    if (!(idx_x >= 0 && idx_Er >= 0 && idx_Wo >= 0 && idx_bo >= 0 && ncand == 4)) {
        int wi = (n_in >= 9) ? 3 : 2;
        idx_x = 0; cand[0] = 1; cand[1] = wi; cand[2] = wi + 1; cand[3] = wi + 2;
        idx_Er = wi + 3; idx_Wo = wi + 4; idx_bo = wi + 5; ncand = 4;
    }

    const float* x  = (const float*)d_in[idx_x];
    const float* Er = (const float*)d_in[idx_Er];
    const float* Wo = (const float*)d_in[idx_Wo];
    const float* bo = (const float*)d_in[idx_bo];
    float* out = (float*)d_out;

    const int PROJ_SMEM = (192*64 + 128*64) * (int)sizeof(float);            // 81920 B
    const int ATTN_SMEM = (4*4096 + 64*128) * (int)sizeof(float);            // 98304 B
    cudaFuncSetAttribute(proj_kernel, cudaFuncAttributeMaxDynamicSharedMemorySize, PROJ_SMEM);
    cudaFuncSetAttribute(attn_kernel, cudaFuncAttributeMaxDynamicSharedMemorySize, ATTN_SMEM);

    select_inputs<<<1, 256>>>((const float*)d_in[cand[0]], (const float*)d_in[cand[1]],
                              (const float*)d_in[cand[2]], (const float*)d_in[cand[3]],
                              (idx_x == 0) ? 1 : 0);
    proj_kernel<<<dim3(TLEN/128, HEADS_N, BATCH), 256, PROJ_SMEM>>>(x);
    vmean_kernel<<<BATCH*HEADS_N, 256>>>();
    attn_kernel<<<dim3(TLEN/64, HEADS_N, BATCH), 256, ATTN_SMEM>>>(Er);
    outproj_kernel<<<dim3((BATCH*TLEN)/64, EDIM/64), 256>>>(Wo, bo, out);
}